// round 1
// baseline (speedup 1.0000x reference)
#include <cuda_runtime.h>

#define BB 16
#define NN 2048
#define DD 64
#define SCALE 0.125f
#define TS 68   // smem row stride (floats): 64 + 4 padding, conflict-free frag loads

// 16 MB scratch for reciprocal softmax denominators (denominator is over batch dim)
__device__ float g_rdenom[(size_t)NN * NN];

__device__ __forceinline__ float ftf32(float x) {
    unsigned u;
    asm("cvt.rna.tf32.f32 %0, %1;" : "=r"(u) : "f"(x));
    return __uint_as_float(u);
}

__device__ __forceinline__ void mma_tf32(float c[4],
                                         unsigned a0, unsigned a1, unsigned a2, unsigned a3,
                                         unsigned b0, unsigned b1) {
    asm volatile(
        "mma.sync.aligned.m16n8k8.row.col.f32.tf32.tf32.f32 "
        "{%0,%1,%2,%3}, {%4,%5,%6,%7}, {%8,%9}, {%0,%1,%2,%3};"
        : "+f"(c[0]), "+f"(c[1]), "+f"(c[2]), "+f"(c[3])
        : "r"(a0), "r"(a1), "r"(a2), "r"(a3), "r"(b0), "r"(b1));
}

// ---------------------------------------------------------------------------
// Kernel 1: rdenom[q,k] = 1 / sum_b exp(scale * Q[b,q,:].K[b,k,:])
// Grid: (32 kt, 32 qt), 128 threads (4 warps, 16 rows each of a 64x64 tile)
// ---------------------------------------------------------------------------
__global__ __launch_bounds__(128)
void denom_kernel(const float* __restrict__ Q, const float* __restrict__ Kg) {
    __shared__ float Qs[64][TS];
    __shared__ float Ks[64][TS];
    const int q0 = blockIdx.y * 64, k0 = blockIdx.x * 64;
    const int tid = threadIdx.x;
    const int wid = tid >> 5, lane = tid & 31;
    const int g = lane >> 2, tig = lane & 3;
    const int m0 = wid * 16;

    float dsum[8][4];
#pragma unroll
    for (int i = 0; i < 8; i++) { dsum[i][0] = dsum[i][1] = dsum[i][2] = dsum[i][3] = 0.f; }

    for (int b = 0; b < BB; b++) {
        const float* Qb = Q + ((size_t)b * NN + q0) * DD;
        const float* Kb = Kg + ((size_t)b * NN + k0) * DD;
#pragma unroll
        for (int i = 0; i < 8; i++) {
            int idx = tid + i * 128;
            int r = idx >> 4, c = (idx & 15) << 2;
            float4 vq = *reinterpret_cast<const float4*>(Qb + r * DD + c);
            float4 vk = *reinterpret_cast<const float4*>(Kb + r * DD + c);
            vq.x = ftf32(vq.x); vq.y = ftf32(vq.y); vq.z = ftf32(vq.z); vq.w = ftf32(vq.w);
            vk.x = ftf32(vk.x); vk.y = ftf32(vk.y); vk.z = ftf32(vk.z); vk.w = ftf32(vk.w);
            *reinterpret_cast<float4*>(&Qs[r][c]) = vq;
            *reinterpret_cast<float4*>(&Ks[r][c]) = vk;
        }
        __syncthreads();

        float cacc[8][4];
#pragma unroll
        for (int i = 0; i < 8; i++) { cacc[i][0] = cacc[i][1] = cacc[i][2] = cacc[i][3] = 0.f; }

#pragma unroll
        for (int kk = 0; kk < 64; kk += 8) {
            unsigned a0 = __float_as_uint(Qs[m0 + g][kk + tig]);
            unsigned a1 = __float_as_uint(Qs[m0 + g + 8][kk + tig]);
            unsigned a2 = __float_as_uint(Qs[m0 + g][kk + tig + 4]);
            unsigned a3 = __float_as_uint(Qs[m0 + g + 8][kk + tig + 4]);
#pragma unroll
            for (int nb = 0; nb < 8; nb++) {
                unsigned b0 = __float_as_uint(Ks[nb * 8 + g][kk + tig]);
                unsigned b1 = __float_as_uint(Ks[nb * 8 + g][kk + tig + 4]);
                mma_tf32(cacc[nb], a0, a1, a2, a3, b0, b1);
            }
        }
#pragma unroll
        for (int nb = 0; nb < 8; nb++) {
#pragma unroll
            for (int j = 0; j < 4; j++) dsum[nb][j] += __expf(cacc[nb][j] * SCALE);
        }
        __syncthreads();
    }

    // Write reciprocal denominators (fragment-owned positions, 8B stores)
#pragma unroll
    for (int nb = 0; nb < 8; nb++) {
        int col = k0 + nb * 8 + 2 * tig;
        int r1 = q0 + m0 + g;
        float2 v0 = make_float2(1.f / dsum[nb][0], 1.f / dsum[nb][1]);
        float2 v1 = make_float2(1.f / dsum[nb][2], 1.f / dsum[nb][3]);
        *reinterpret_cast<float2*>(&g_rdenom[(size_t)r1 * NN + col]) = v0;
        *reinterpret_cast<float2*>(&g_rdenom[((size_t)r1 + 8) * NN + col]) = v1;
    }
}

// ---------------------------------------------------------------------------
// Kernel 2: out[b,q,:] = sum_k exp(scale*s[b,q,k]) * rdenom[q,k] * V[b,k,:]
// Grid: (32 qt, 16 b), 128 threads. Recomputes S per k-tile (flash-style).
// ---------------------------------------------------------------------------
extern __shared__ float sm2[];

__global__ __launch_bounds__(128)
void attn_kernel(const float* __restrict__ Q, const float* __restrict__ Kg,
                 const float* __restrict__ V, float* __restrict__ out) {
    float* Qs = sm2;                 // [64][TS]
    float* Ks = sm2 + 64 * TS;       // [64][TS]
    float* Vs = sm2 + 2 * 64 * TS;   // [64][TS]
    float* Ps = sm2 + 3 * 64 * TS;   // [64][TS], per-warp 16-row slices

    const int qt = blockIdx.x, b = blockIdx.y;
    const int q0 = qt * 64;
    const int tid = threadIdx.x;
    const int wid = tid >> 5, lane = tid & 31;
    const int g = lane >> 2, tig = lane & 3;
    const int m0 = wid * 16;

    // Load Q tile once (tf32-rounded)
    const float* Qb = Q + ((size_t)b * NN + q0) * DD;
#pragma unroll
    for (int i = 0; i < 8; i++) {
        int idx = tid + i * 128;
        int r = idx >> 4, c = (idx & 15) << 2;
        float4 vq = *reinterpret_cast<const float4*>(Qb + r * DD + c);
        vq.x = ftf32(vq.x); vq.y = ftf32(vq.y); vq.z = ftf32(vq.z); vq.w = ftf32(vq.w);
        *reinterpret_cast<float4*>(&Qs[r * TS + c]) = vq;
    }

    float oacc[8][4];
#pragma unroll
    for (int i = 0; i < 8; i++) { oacc[i][0] = oacc[i][1] = oacc[i][2] = oacc[i][3] = 0.f; }

    for (int kt = 0; kt < 32; kt++) {
        const int k0 = kt * 64;
        const float* Kb = Kg + ((size_t)b * NN + k0) * DD;
        const float* Vb = V + ((size_t)b * NN + k0) * DD;

        __syncthreads();   // previous iteration done reading Ks/Vs (also fences Q load on iter 0)
#pragma unroll
        for (int i = 0; i < 8; i++) {
            int idx = tid + i * 128;
            int r = idx >> 4, c = (idx & 15) << 2;
            float4 vk = *reinterpret_cast<const float4*>(Kb + r * DD + c);
            float4 vv = *reinterpret_cast<const float4*>(Vb + r * DD + c);
            vk.x = ftf32(vk.x); vk.y = ftf32(vk.y); vk.z = ftf32(vk.z); vk.w = ftf32(vk.w);
            vv.x = ftf32(vv.x); vv.y = ftf32(vv.y); vv.z = ftf32(vv.z); vv.w = ftf32(vv.w);
            *reinterpret_cast<float4*>(&Ks[r * TS + c]) = vk;
            *reinterpret_cast<float4*>(&Vs[r * TS + c]) = vv;
        }
        __syncthreads();

        // S = Q . K^T  (this warp's 16 rows x 64 cols)
        float cacc[8][4];
#pragma unroll
        for (int i = 0; i < 8; i++) { cacc[i][0] = cacc[i][1] = cacc[i][2] = cacc[i][3] = 0.f; }
#pragma unroll
        for (int kk = 0; kk < 64; kk += 8) {
            unsigned a0 = __float_as_uint(Qs[(m0 + g) * TS + kk + tig]);
            unsigned a1 = __float_as_uint(Qs[(m0 + g + 8) * TS + kk + tig]);
            unsigned a2 = __float_as_uint(Qs[(m0 + g) * TS + kk + tig + 4]);
            unsigned a3 = __float_as_uint(Qs[(m0 + g + 8) * TS + kk + tig + 4]);
#pragma unroll
            for (int nb = 0; nb < 8; nb++) {
                unsigned b0 = __float_as_uint(Ks[(nb * 8 + g) * TS + kk + tig]);
                unsigned b1 = __float_as_uint(Ks[(nb * 8 + g) * TS + kk + tig + 4]);
                mma_tf32(cacc[nb], a0, a1, a2, a3, b0, b1);
            }
        }

        // P = exp(scale*S) * rdenom, staged to per-warp SMEM slice (tf32-rounded)
        const float* rd = g_rdenom + (size_t)(q0 + m0 + g) * NN + k0;
#pragma unroll
        for (int nb = 0; nb < 8; nb++) {
            int col = nb * 8 + 2 * tig;
            float2 r0 = *reinterpret_cast<const float2*>(rd + col);
            float2 r1 = *reinterpret_cast<const float2*>(rd + (size_t)8 * NN + col);
            float p0 = __expf(cacc[nb][0] * SCALE) * r0.x;
            float p1 = __expf(cacc[nb][1] * SCALE) * r0.y;
            float p2 = __expf(cacc[nb][2] * SCALE) * r1.x;
            float p3 = __expf(cacc[nb][3] * SCALE) * r1.y;
            float2 s0 = make_float2(ftf32(p0), ftf32(p1));
            float2 s1 = make_float2(ftf32(p2), ftf32(p3));
            *reinterpret_cast<float2*>(&Ps[(m0 + g) * TS + col]) = s0;
            *reinterpret_cast<float2*>(&Ps[(m0 + g + 8) * TS + col]) = s1;
        }
        __syncwarp();   // each warp's O rows consume only its own P rows

        // O += P . V
#pragma unroll
        for (int kk = 0; kk < 64; kk += 8) {
            unsigned a0 = __float_as_uint(Ps[(m0 + g) * TS + kk + tig]);
            unsigned a1 = __float_as_uint(Ps[(m0 + g + 8) * TS + kk + tig]);
            unsigned a2 = __float_as_uint(Ps[(m0 + g) * TS + kk + tig + 4]);
            unsigned a3 = __float_as_uint(Ps[(m0 + g + 8) * TS + kk + tig + 4]);
#pragma unroll
            for (int nb = 0; nb < 8; nb++) {
                unsigned b0 = __float_as_uint(Vs[(kk + tig) * TS + nb * 8 + g]);
                unsigned b1 = __float_as_uint(Vs[(kk + tig + 4) * TS + nb * 8 + g]);
                mma_tf32(oacc[nb], a0, a1, a2, a3, b0, b1);
            }
        }
    }

    // Write output
    float* ob = out + ((size_t)b * NN + q0 + m0) * DD;
#pragma unroll
    for (int nb = 0; nb < 8; nb++) {
        int col = nb * 8 + 2 * tig;
        *reinterpret_cast<float2*>(&ob[(size_t)g * DD + col]) =
            make_float2(oacc[nb][0], oacc[nb][1]);
        *reinterpret_cast<float2*>(&ob[((size_t)g + 8) * DD + col]) =
            make_float2(oacc[nb][2], oacc[nb][3]);
    }
}

extern "C" void kernel_launch(void* const* d_in, const int* in_sizes, int n_in,
                              void* d_out, int out_size) {
    const float* Q = (const float*)d_in[0];
    const float* K = (const float*)d_in[1];
    const float* V = (const float*)d_in[2];
    float* out = (float*)d_out;

    denom_kernel<<<dim3(32, 32), 128>>>(Q, K);

    const int smem2 = 4 * 64 * TS * (int)sizeof(float);  // 69632 B
    cudaFuncSetAttribute(attn_kernel, cudaFuncAttributeMaxDynamicSharedMemorySize, smem2);
    attn_kernel<<<dim3(32, 16), 128, smem2>>>(Q, K, V, out);
}

// round 2
// speedup vs baseline: 1.0762x; 1.0762x over previous
#include <cuda_runtime.h>

#define BB 16
#define NN 2048
#define DD 64
#define SCALE 0.125f
#define TS 72   // smem row stride (floats): 64 + 8 -> row stride mod 32 banks = 8, conflict-free paired loads

// 16 MB scratch for reciprocal softmax denominators (softmax is over the batch dim)
__device__ float g_rdenom[(size_t)NN * NN];

__device__ __forceinline__ float ftf32(float x) {
    unsigned u;
    asm("cvt.rna.tf32.f32 %0, %1;" : "=r"(u) : "f"(x));
    return __uint_as_float(u);
}

__device__ __forceinline__ void mma_tf32(float c[4],
                                         float a0, float a1, float a2, float a3,
                                         float b0, float b1) {
    asm volatile(
        "mma.sync.aligned.m16n8k8.row.col.f32.tf32.tf32.f32 "
        "{%0,%1,%2,%3}, {%4,%5,%6,%7}, {%8,%9}, {%0,%1,%2,%3};"
        : "+f"(c[0]), "+f"(c[1]), "+f"(c[2]), "+f"(c[3])
        : "r"(__float_as_uint(a0)), "r"(__float_as_uint(a1)),
          "r"(__float_as_uint(a2)), "r"(__float_as_uint(a3)),
          "r"(__float_as_uint(b0)), "r"(__float_as_uint(b1)));
}

// Column permutation within each 8-col group: col c -> (c&~7) + 2*(c&3) + ((c>>2)&1).
// Then A-frag (cols t, t+4) and B-frag (cols t, t+4) are adjacent -> one LDS.64.

// ---------------------------------------------------------------------------
// Kernel 1: rdenom[q,k] = 1 / sum_b exp(scale * Q[b,q,:].K[b,k,:])
// Grid: (32 kt, 16 qt). 256 threads = 8 warps; q-tile 128, k-tile 64.
// ---------------------------------------------------------------------------
extern __shared__ float smd[];

__global__ __launch_bounds__(256, 2)
void denom_kernel(const float* __restrict__ Q, const float* __restrict__ Kg) {
    float* Qs = smd;             // [128][TS], permuted cols
    float* Ks = smd + 128 * TS;  // [64][TS], permuted cols

    const int q0 = blockIdx.y * 128, k0 = blockIdx.x * 64;
    const int tid = threadIdx.x;
    const int wid = tid >> 5, lane = tid & 31;
    const int g = lane >> 2, tig = lane & 3;
    const int m0 = wid * 16;

    float dsum[8][4];
#pragma unroll
    for (int i = 0; i < 8; i++) { dsum[i][0] = dsum[i][1] = dsum[i][2] = dsum[i][3] = 0.f; }

    for (int b = 0; b < BB; b++) {
        const float* Qb = Q + ((size_t)b * NN + q0) * DD;
        const float* Kb = Kg + ((size_t)b * NN + k0) * DD;
#pragma unroll
        for (int i = 0; i < 8; i++) {      // Q: 128 rows
            int idx = tid + i * 256;
            int r = idx >> 4, c = (idx & 15) << 2;
            float4 v = *reinterpret_cast<const float4*>(Qb + r * DD + c);
            int base = r * TS + (c & ~7) + ((c >> 2) & 1);
            Qs[base + 0] = ftf32(v.x); Qs[base + 2] = ftf32(v.y);
            Qs[base + 4] = ftf32(v.z); Qs[base + 6] = ftf32(v.w);
        }
#pragma unroll
        for (int i = 0; i < 4; i++) {      // K: 64 rows
            int idx = tid + i * 256;
            int r = idx >> 4, c = (idx & 15) << 2;
            float4 v = *reinterpret_cast<const float4*>(Kb + r * DD + c);
            int base = r * TS + (c & ~7) + ((c >> 2) & 1);
            Ks[base + 0] = ftf32(v.x); Ks[base + 2] = ftf32(v.y);
            Ks[base + 4] = ftf32(v.z); Ks[base + 6] = ftf32(v.w);
        }
        __syncthreads();

        float cacc[8][4];
#pragma unroll
        for (int i = 0; i < 8; i++) { cacc[i][0] = cacc[i][1] = cacc[i][2] = cacc[i][3] = 0.f; }

#pragma unroll
        for (int kk = 0; kk < 64; kk += 8) {
            const float* qr = &Qs[(m0 + g) * TS + kk + 2 * tig];
            float2 A0 = *reinterpret_cast<const float2*>(qr);            // (g,tig),(g,tig+4)
            float2 A1 = *reinterpret_cast<const float2*>(qr + 8 * TS);   // (g+8,...)
#pragma unroll
            for (int nb = 0; nb < 8; nb++) {
                float2 Bf = *reinterpret_cast<const float2*>(&Ks[(nb * 8 + g) * TS + kk + 2 * tig]);
                mma_tf32(cacc[nb], A0.x, A1.x, A0.y, A1.y, Bf.x, Bf.y);
            }
        }
#pragma unroll
        for (int nb = 0; nb < 8; nb++) {
#pragma unroll
            for (int j = 0; j < 4; j++) dsum[nb][j] += __expf(cacc[nb][j] * SCALE);
        }
        __syncthreads();
    }

#pragma unroll
    for (int nb = 0; nb < 8; nb++) {
        int col = k0 + nb * 8 + 2 * tig;
        int r1 = q0 + m0 + g;
        float2 v0 = make_float2(1.f / dsum[nb][0], 1.f / dsum[nb][1]);
        float2 v1 = make_float2(1.f / dsum[nb][2], 1.f / dsum[nb][3]);
        *reinterpret_cast<float2*>(&g_rdenom[(size_t)r1 * NN + col]) = v0;
        *reinterpret_cast<float2*>(&g_rdenom[((size_t)r1 + 8) * NN + col]) = v1;
    }
}

// ---------------------------------------------------------------------------
// Kernel 2: out[b,q,:] = sum_k exp(scale*s[b,q,k]) * rdenom[q,k] * V[b,k,:]
// Grid: (16 qt, 16 b). 256 threads = 8 warps; q-tile 128, k-tile 64.
// P never touches SMEM: accumulator fragments -> A fragments via quad shuffles.
// ---------------------------------------------------------------------------
extern __shared__ float sm2[];

__global__ __launch_bounds__(256, 2)
void attn_kernel(const float* __restrict__ Q, const float* __restrict__ Kg,
                 const float* __restrict__ V, float* __restrict__ out) {
    float* Qs = sm2;              // [128][TS], permuted
    float* Ks = sm2 + 128 * TS;   // [64][TS], permuted
    float* Vs = sm2 + 192 * TS;   // [64][TS], plain

    const int q0 = blockIdx.x * 128, b = blockIdx.y;
    const int tid = threadIdx.x;
    const int wid = tid >> 5, lane = tid & 31;
    const int g = lane >> 2, tig = lane & 3;
    const int m0 = wid * 16;
    const int src0 = (lane & ~3) | (tig >> 1);  // quad lane holding col tig
    const int src1 = src0 + 2;                  // quad lane holding col tig+4
    const bool hi = tig & 1;

    // Load Q tile once (tf32-rounded, permuted)
    const float* Qb = Q + ((size_t)b * NN + q0) * DD;
#pragma unroll
    for (int i = 0; i < 8; i++) {
        int idx = tid + i * 256;
        int r = idx >> 4, c = (idx & 15) << 2;
        float4 v = *reinterpret_cast<const float4*>(Qb + r * DD + c);
        int base = r * TS + (c & ~7) + ((c >> 2) & 1);
        Qs[base + 0] = ftf32(v.x); Qs[base + 2] = ftf32(v.y);
        Qs[base + 4] = ftf32(v.z); Qs[base + 6] = ftf32(v.w);
    }

    float oacc[8][4];
#pragma unroll
    for (int i = 0; i < 8; i++) { oacc[i][0] = oacc[i][1] = oacc[i][2] = oacc[i][3] = 0.f; }

    const float* rdbase = g_rdenom + (size_t)(q0 + m0 + g) * NN;

    for (int kt = 0; kt < 32; kt++) {
        const int k0 = kt * 64;
        const float* Kb = Kg + ((size_t)b * NN + k0) * DD;
        const float* Vb = V + ((size_t)b * NN + k0) * DD;

        __syncthreads();   // prior iter done reading Ks/Vs (also fences Qs on iter 0)
#pragma unroll
        for (int i = 0; i < 4; i++) {
            int idx = tid + i * 256;
            int r = idx >> 4, c = (idx & 15) << 2;
            float4 vk = *reinterpret_cast<const float4*>(Kb + r * DD + c);
            float4 vv = *reinterpret_cast<const float4*>(Vb + r * DD + c);
            int base = r * TS + (c & ~7) + ((c >> 2) & 1);
            Ks[base + 0] = ftf32(vk.x); Ks[base + 2] = ftf32(vk.y);
            Ks[base + 4] = ftf32(vk.z); Ks[base + 6] = ftf32(vk.w);
            vv.x = ftf32(vv.x); vv.y = ftf32(vv.y); vv.z = ftf32(vv.z); vv.w = ftf32(vv.w);
            *reinterpret_cast<float4*>(&Vs[r * TS + c]) = vv;
        }
        __syncthreads();

        // S = Q . K^T  (this warp's 16 rows x 64 cols)
        float cacc[8][4];
#pragma unroll
        for (int i = 0; i < 8; i++) { cacc[i][0] = cacc[i][1] = cacc[i][2] = cacc[i][3] = 0.f; }
#pragma unroll
        for (int kk = 0; kk < 64; kk += 8) {
            const float* qr = &Qs[(m0 + g) * TS + kk + 2 * tig];
            float2 A0 = *reinterpret_cast<const float2*>(qr);
            float2 A1 = *reinterpret_cast<const float2*>(qr + 8 * TS);
#pragma unroll
            for (int nb = 0; nb < 8; nb++) {
                float2 Bf = *reinterpret_cast<const float2*>(&Ks[(nb * 8 + g) * TS + kk + 2 * tig]);
                mma_tf32(cacc[nb], A0.x, A1.x, A0.y, A1.y, Bf.x, Bf.y);
            }
        }

        // P = exp(scale*S)*rdenom in regs; frag-convert via quad shuffles; O += P.V
        const float* rd = rdbase + k0;
#pragma unroll
        for (int nb = 0; nb < 8; nb++) {
            int col = nb * 8 + 2 * tig;
            float2 r0 = *reinterpret_cast<const float2*>(rd + col);
            float2 r1 = *reinterpret_cast<const float2*>(rd + (size_t)8 * NN + col);
            float p0 = ftf32(__expf(cacc[nb][0] * SCALE) * r0.x);  // (g,    2tig  )
            float p1 = ftf32(__expf(cacc[nb][1] * SCALE) * r0.y);  // (g,    2tig+1)
            float p2 = ftf32(__expf(cacc[nb][2] * SCALE) * r1.x);  // (g+8,  2tig  )
            float p3 = ftf32(__expf(cacc[nb][3] * SCALE) * r1.y);  // (g+8,  2tig+1)

            float u, w, a0, a1, a2, a3;
            u = __shfl_sync(0xFFFFFFFFu, p0, src0);
            w = __shfl_sync(0xFFFFFFFFu, p1, src0);
            a0 = hi ? w : u;                                  // (g,   tig)
            u = __shfl_sync(0xFFFFFFFFu, p2, src0);
            w = __shfl_sync(0xFFFFFFFFu, p3, src0);
            a1 = hi ? w : u;                                  // (g+8, tig)
            u = __shfl_sync(0xFFFFFFFFu, p0, src1);
            w = __shfl_sync(0xFFFFFFFFu, p1, src1);
            a2 = hi ? w : u;                                  // (g,   tig+4)
            u = __shfl_sync(0xFFFFFFFFu, p2, src1);
            w = __shfl_sync(0xFFFFFFFFu, p3, src1);
            a3 = hi ? w : u;                                  // (g+8, tig+4)

            const float* vrow0 = &Vs[(nb * 8 + tig) * TS + g];
            const float* vrow1 = vrow0 + 4 * TS;
#pragma unroll
            for (int n2 = 0; n2 < 8; n2++) {
                float b0 = vrow0[n2 * 8];
                float b1 = vrow1[n2 * 8];
                mma_tf32(oacc[n2], a0, a1, a2, a3, b0, b1);
            }
        }
    }

    // Write output
    float* ob = out + ((size_t)b * NN + q0 + m0) * DD;
#pragma unroll
    for (int nb = 0; nb < 8; nb++) {
        int col = nb * 8 + 2 * tig;
        *reinterpret_cast<float2*>(&ob[(size_t)g * DD + col]) =
            make_float2(oacc[nb][0], oacc[nb][1]);
        *reinterpret_cast<float2*>(&ob[((size_t)g + 8) * DD + col]) =
            make_float2(oacc[nb][2], oacc[nb][3]);
    }
}

extern "C" void kernel_launch(void* const* d_in, const int* in_sizes, int n_in,
                              void* d_out, int out_size) {
    const float* Q = (const float*)d_in[0];
    const float* K = (const float*)d_in[1];
    const float* V = (const float*)d_in[2];
    float* out = (float*)d_out;

    const int smemd = 192 * TS * (int)sizeof(float);   // 55296 B
    const int smem2 = 256 * TS * (int)sizeof(float);   // 73728 B
    cudaFuncSetAttribute(denom_kernel, cudaFuncAttributeMaxDynamicSharedMemorySize, smemd);
    cudaFuncSetAttribute(attn_kernel, cudaFuncAttributeMaxDynamicSharedMemorySize, smem2);

    denom_kernel<<<dim3(32, 16), 256, smemd>>>(Q, K);
    attn_kernel<<<dim3(16, 16), 256, smem2>>>(Q, K, V, out);
}

// round 3
// speedup vs baseline: 1.1484x; 1.0671x over previous
#include <cuda_runtime.h>

#define BB 16
#define NN 2048
#define DD 64
#define SCALE 0.125f
#define TS 72   // smem row stride (floats): 64+8 -> stride mod 32 banks = 8, conflict-free frag loads

// 16 MB scratch for reciprocal softmax denominators (softmax is over the batch dim).
// NOTE: stored with k-columns permuted within each 8-group (matches the K-row permutation).
__device__ float g_rdenom[(size_t)NN * NN];

__device__ __forceinline__ float ftf32(float x) {
    unsigned u;
    asm("cvt.rna.tf32.f32 %0, %1;" : "=r"(u) : "f"(x));
    return __uint_as_float(u);
}

__device__ __forceinline__ void mma_tf32(float c[4],
                                         float a0, float a1, float a2, float a3,
                                         float b0, float b1) {
    asm volatile(
        "mma.sync.aligned.m16n8k8.row.col.f32.tf32.tf32.f32 "
        "{%0,%1,%2,%3}, {%4,%5,%6,%7}, {%8,%9}, {%0,%1,%2,%3};"
        : "+f"(c[0]), "+f"(c[1]), "+f"(c[2]), "+f"(c[3])
        : "r"(__float_as_uint(a0)), "r"(__float_as_uint(a1)),
          "r"(__float_as_uint(a2)), "r"(__float_as_uint(a3)),
          "r"(__float_as_uint(b0)), "r"(__float_as_uint(b1)));
}

// Column permutation within each 8-col group: col c -> (c&~7) + 2*(c&3) + ((c>>2)&1)
// (makes A/B fragment pair loads a single LDS.64).
// K-row permutation within each 8-row group: row j -> (j&~7) + 2*(j&3) + ((j>>2)&1)
// (makes the S-accumulator layout equal the PV A-fragment layout up to register renaming:
//  acc slot c0 holds k=t, c1 holds k=t+4, so (a0,a1,a2,a3) = (c0,c2,c1,c3). Zero shuffles.)
__device__ __forceinline__ int kperm(int r) {
    return (r & ~7) | ((r & 3) << 1) | ((r >> 2) & 1);
}

// ---------------------------------------------------------------------------
// Kernel 1: rdenom[q,k] = 1 / sum_b exp(scale * Q[b,q,:].K[b,k,:])
// Grid: (32 kt, 16 qt). 256 threads = 8 warps; q-tile 128, k-tile 64.
// ---------------------------------------------------------------------------
extern __shared__ float smd[];

__global__ __launch_bounds__(256, 2)
void denom_kernel(const float* __restrict__ Q, const float* __restrict__ Kg) {
    float* Qs = smd;             // [128][TS], permuted cols
    float* Ks = smd + 128 * TS;  // [64][TS], permuted cols + permuted rows

    const int q0 = blockIdx.y * 128, k0 = blockIdx.x * 64;
    const int tid = threadIdx.x;
    const int wid = tid >> 5, lane = tid & 31;
    const int g = lane >> 2, tig = lane & 3;
    const int m0 = wid * 16;

    float dsum[8][4];
#pragma unroll
    for (int i = 0; i < 8; i++) { dsum[i][0] = dsum[i][1] = dsum[i][2] = dsum[i][3] = 0.f; }

    for (int b = 0; b < BB; b++) {
        const float* Qb = Q + ((size_t)b * NN + q0) * DD;
        const float* Kb = Kg + ((size_t)b * NN + k0) * DD;
#pragma unroll
        for (int i = 0; i < 8; i++) {      // Q: 128 rows
            int idx = tid + i * 256;
            int r = idx >> 4, c = (idx & 15) << 2;
            float4 v = *reinterpret_cast<const float4*>(Qb + r * DD + c);
            int base = r * TS + (c & ~7) + ((c >> 2) & 1);
            Qs[base + 0] = ftf32(v.x); Qs[base + 2] = ftf32(v.y);
            Qs[base + 4] = ftf32(v.z); Qs[base + 6] = ftf32(v.w);
        }
#pragma unroll
        for (int i = 0; i < 4; i++) {      // K: 64 rows, row-permuted
            int idx = tid + i * 256;
            int r = idx >> 4, c = (idx & 15) << 2;
            float4 v = *reinterpret_cast<const float4*>(Kb + r * DD + c);
            int base = kperm(r) * TS + (c & ~7) + ((c >> 2) & 1);
            Ks[base + 0] = ftf32(v.x); Ks[base + 2] = ftf32(v.y);
            Ks[base + 4] = ftf32(v.z); Ks[base + 6] = ftf32(v.w);
        }
        __syncthreads();

        float cacc[8][4];
#pragma unroll
        for (int i = 0; i < 8; i++) { cacc[i][0] = cacc[i][1] = cacc[i][2] = cacc[i][3] = 0.f; }

#pragma unroll
        for (int kk = 0; kk < 64; kk += 8) {
            const float* qr = &Qs[(m0 + g) * TS + kk + 2 * tig];
            float2 A0 = *reinterpret_cast<const float2*>(qr);            // (g,tig),(g,tig+4)
            float2 A1 = *reinterpret_cast<const float2*>(qr + 8 * TS);   // (g+8,...)
#pragma unroll
            for (int nb = 0; nb < 8; nb++) {
                float2 Bf = *reinterpret_cast<const float2*>(&Ks[(nb * 8 + g) * TS + kk + 2 * tig]);
                mma_tf32(cacc[nb], A0.x, A1.x, A0.y, A1.y, Bf.x, Bf.y);
            }
        }
#pragma unroll
        for (int nb = 0; nb < 8; nb++) {
#pragma unroll
            for (int j = 0; j < 4; j++) dsum[nb][j] += __expf(cacc[nb][j] * SCALE);
        }
        __syncthreads();
    }

    // Storage column (2t, 2t+1) holds actual k = (t, t+4): consistent with attn_kernel reads.
#pragma unroll
    for (int nb = 0; nb < 8; nb++) {
        int col = k0 + nb * 8 + 2 * tig;
        int r1 = q0 + m0 + g;
        float2 v0 = make_float2(1.f / dsum[nb][0], 1.f / dsum[nb][1]);
        float2 v1 = make_float2(1.f / dsum[nb][2], 1.f / dsum[nb][3]);
        *reinterpret_cast<float2*>(&g_rdenom[(size_t)r1 * NN + col]) = v0;
        *reinterpret_cast<float2*>(&g_rdenom[((size_t)r1 + 8) * NN + col]) = v1;
    }
}

// ---------------------------------------------------------------------------
// Kernel 2: out[b,q,:] = sum_k exp(scale*s[b,q,k]) * rdenom[q,k] * V[b,k,:]
// Grid: (16 qt, 16 b). 256 threads = 8 warps; q-tile 128, k-tile 64.
// K rows permuted in SMEM -> S-accumulator IS the PV A-fragment (reg renaming only).
// ---------------------------------------------------------------------------
extern __shared__ float sm2[];

__global__ __launch_bounds__(256, 2)
void attn_kernel(const float* __restrict__ Q, const float* __restrict__ Kg,
                 const float* __restrict__ V, float* __restrict__ out) {
    float* Qs = sm2;              // [128][TS], permuted cols
    float* Ks = sm2 + 128 * TS;   // [64][TS], permuted cols + rows
    float* Vs = sm2 + 192 * TS;   // [64][TS], plain

    const int q0 = blockIdx.x * 128, b = blockIdx.y;
    const int tid = threadIdx.x;
    const int wid = tid >> 5, lane = tid & 31;
    const int g = lane >> 2, tig = lane & 3;
    const int m0 = wid * 16;

    // Load Q tile once (tf32-rounded, permuted cols)
    const float* Qb = Q + ((size_t)b * NN + q0) * DD;
#pragma unroll
    for (int i = 0; i < 8; i++) {
        int idx = tid + i * 256;
        int r = idx >> 4, c = (idx & 15) << 2;
        float4 v = *reinterpret_cast<const float4*>(Qb + r * DD + c);
        int base = r * TS + (c & ~7) + ((c >> 2) & 1);
        Qs[base + 0] = ftf32(v.x); Qs[base + 2] = ftf32(v.y);
        Qs[base + 4] = ftf32(v.z); Qs[base + 6] = ftf32(v.w);
    }

    float oacc[8][4];
#pragma unroll
    for (int i = 0; i < 8; i++) { oacc[i][0] = oacc[i][1] = oacc[i][2] = oacc[i][3] = 0.f; }

    const float* rdbase = g_rdenom + (size_t)(q0 + m0 + g) * NN;

    for (int kt = 0; kt < 32; kt++) {
        const int k0 = kt * 64;
        const float* Kb = Kg + ((size_t)b * NN + k0) * DD;
        const float* Vb = V + ((size_t)b * NN + k0) * DD;

        __syncthreads();   // prior iter done reading Ks/Vs (also fences Qs on iter 0)
#pragma unroll
        for (int i = 0; i < 4; i++) {
            int idx = tid + i * 256;
            int r = idx >> 4, c = (idx & 15) << 2;
            float4 vk = *reinterpret_cast<const float4*>(Kb + r * DD + c);
            float4 vv = *reinterpret_cast<const float4*>(Vb + r * DD + c);
            int base = kperm(r) * TS + (c & ~7) + ((c >> 2) & 1);
            Ks[base + 0] = ftf32(vk.x); Ks[base + 2] = ftf32(vk.y);
            Ks[base + 4] = ftf32(vk.z); Ks[base + 6] = ftf32(vk.w);
            vv.x = ftf32(vv.x); vv.y = ftf32(vv.y); vv.z = ftf32(vv.z); vv.w = ftf32(vv.w);
            *reinterpret_cast<float4*>(&Vs[r * TS + c]) = vv;
        }
        __syncthreads();

        // S = Q . K^T  (this warp's 16 rows x 64 permuted cols)
        float cacc[8][4];
#pragma unroll
        for (int i = 0; i < 8; i++) { cacc[i][0] = cacc[i][1] = cacc[i][2] = cacc[i][3] = 0.f; }
#pragma unroll
        for (int kk = 0; kk < 64; kk += 8) {
            const float* qr = &Qs[(m0 + g) * TS + kk + 2 * tig];
            float2 A0 = *reinterpret_cast<const float2*>(qr);
            float2 A1 = *reinterpret_cast<const float2*>(qr + 8 * TS);
#pragma unroll
            for (int nb = 0; nb < 8; nb++) {
                float2 Bf = *reinterpret_cast<const float2*>(&Ks[(nb * 8 + g) * TS + kk + 2 * tig]);
                mma_tf32(cacc[nb], A0.x, A1.x, A0.y, A1.y, Bf.x, Bf.y);
            }
        }

        // P = exp(scale*S)*rdenom entirely in registers.
        // Because K rows were permuted, c0 holds actual k=tig, c1 holds k=tig+4:
        // the PV A-fragment is (c0, c2, c1, c3). No SMEM stage, no shuffles.
        const float* rd = rdbase + k0;
#pragma unroll
        for (int nb = 0; nb < 8; nb++) {
            int col = nb * 8 + 2 * tig;
            float2 r0 = *reinterpret_cast<const float2*>(rd + col);
            float2 r1 = *reinterpret_cast<const float2*>(rd + (size_t)8 * NN + col);
            float a0 = ftf32(__expf(cacc[nb][0] * SCALE) * r0.x);  // (q=g,    k=tig  )
            float a2 = ftf32(__expf(cacc[nb][1] * SCALE) * r0.y);  // (q=g,    k=tig+4)
            float a1 = ftf32(__expf(cacc[nb][2] * SCALE) * r1.x);  // (q=g+8,  k=tig  )
            float a3 = ftf32(__expf(cacc[nb][3] * SCALE) * r1.y);  // (q=g+8,  k=tig+4)

            const float* vrow0 = &Vs[(nb * 8 + tig) * TS + g];   // V row k=tig   (b0)
            const float* vrow1 = vrow0 + 4 * TS;                 // V row k=tig+4 (b1)
#pragma unroll
            for (int n2 = 0; n2 < 8; n2++) {
                float b0 = vrow0[n2 * 8];
                float b1 = vrow1[n2 * 8];
                mma_tf32(oacc[n2], a0, a1, a2, a3, b0, b1);
            }
        }
    }

    // Write output
    float* ob = out + ((size_t)b * NN + q0 + m0) * DD;
#pragma unroll
    for (int nb = 0; nb < 8; nb++) {
        int col = nb * 8 + 2 * tig;
        *reinterpret_cast<float2*>(&ob[(size_t)g * DD + col]) =
            make_float2(oacc[nb][0], oacc[nb][1]);
        *reinterpret_cast<float2*>(&ob[((size_t)g + 8) * DD + col]) =
            make_float2(oacc[nb][2], oacc[nb][3]);
    }
}

extern "C" void kernel_launch(void* const* d_in, const int* in_sizes, int n_in,
                              void* d_out, int out_size) {
    const float* Q = (const float*)d_in[0];
    const float* K = (const float*)d_in[1];
    const float* V = (const float*)d_in[2];
    float* out = (float*)d_out;

    const int smemd = 192 * TS * (int)sizeof(float);   // 55296 B
    const int smem2 = 256 * TS * (int)sizeof(float);   // 73728 B
    cudaFuncSetAttribute(denom_kernel, cudaFuncAttributeMaxDynamicSharedMemorySize, smemd);
    cudaFuncSetAttribute(attn_kernel, cudaFuncAttributeMaxDynamicSharedMemorySize, smem2);

    denom_kernel<<<dim3(32, 16), 256, smemd>>>(Q, K);
    attn_kernel<<<dim3(16, 16), 256, smem2>>>(Q, K, V, out);
}

// round 6
// speedup vs baseline: 1.3023x; 1.1339x over previous
#include <cuda_runtime.h>
#include <cuda_fp16.h>
#include <cstdint>

#define BB 16
#define NN 2048
#define DD 64
#define SCALE 0.125f
#define TS 72   // K1 smem row stride (floats): conflict-free LDS.64 fragment loads

// 134 MB fp16 scratch: E[b][q][k] = exp(scale * S); rescaled in place to P = E / sum_b E
__device__ __half g_E[(size_t)BB * NN * NN];

__device__ __forceinline__ float ftf32(float x) {
    unsigned u;
    asm("cvt.rna.tf32.f32 %0, %1;" : "=r"(u) : "f"(x));
    return __uint_as_float(u);
}

__device__ __forceinline__ uint32_t smem_u32(const void* p) {
    uint32_t a;
    asm("{ .reg .u64 t; cvta.to.shared.u64 t, %1; cvt.u32.u64 %0, t; }" : "=r"(a) : "l"(p));
    return a;
}

__device__ __forceinline__ uint32_t h2_u32(__half2 h) {
    union { __half2 h; uint32_t u; } cvt;
    cvt.h = h;
    return cvt.u;
}

__device__ __forceinline__ void mma_tf32(float c[4],
                                         float a0, float a1, float a2, float a3,
                                         float b0, float b1) {
    asm volatile(
        "mma.sync.aligned.m16n8k8.row.col.f32.tf32.tf32.f32 "
        "{%0,%1,%2,%3}, {%4,%5,%6,%7}, {%8,%9}, {%0,%1,%2,%3};"
        : "+f"(c[0]), "+f"(c[1]), "+f"(c[2]), "+f"(c[3])
        : "r"(__float_as_uint(a0)), "r"(__float_as_uint(a1)),
          "r"(__float_as_uint(a2)), "r"(__float_as_uint(a3)),
          "r"(__float_as_uint(b0)), "r"(__float_as_uint(b1)));
}

__device__ __forceinline__ void mma_f16(float c[4], uint32_t a0, uint32_t a1,
                                        uint32_t a2, uint32_t a3,
                                        uint32_t b0, uint32_t b1) {
    asm volatile(
        "mma.sync.aligned.m16n8k16.row.col.f32.f16.f16.f32 "
        "{%0,%1,%2,%3}, {%4,%5,%6,%7}, {%8,%9}, {%0,%1,%2,%3};"
        : "+f"(c[0]), "+f"(c[1]), "+f"(c[2]), "+f"(c[3])
        : "r"(a0), "r"(a1), "r"(a2), "r"(a3), "r"(b0), "r"(b1));
}

// ---------------------------------------------------------------------------
// Kernel 1: E[b,q,k] = exp(scale * Q[b,q,:].K[b,k,:])    (fp16)
// Grid (32 kt, 16 qt, 16 b), 256 threads. Tile 128q x 64k. Straight-line.
// Column permutation within 8-col groups: c -> (c&~7)+2*(c&3)+((c>>2)&1)
// so A/B fragment pairs (t, t+4) are one LDS.64.
// ---------------------------------------------------------------------------
extern __shared__ float smd[];

__global__ __launch_bounds__(256, 3)
void qk_exp_kernel(const float* __restrict__ Q, const float* __restrict__ Kg) {
    float* Qs = smd;             // [128][TS]
    float* Ks = smd + 128 * TS;  // [64][TS]

    const int q0 = blockIdx.y * 128, k0 = blockIdx.x * 64, b = blockIdx.z;
    const int tid = threadIdx.x;
    const int wid = tid >> 5, lane = tid & 31;
    const int g = lane >> 2, tig = lane & 3;
    const int m0 = wid * 16;

    const float* Qb = Q + ((size_t)b * NN + q0) * DD;
    const float* Kb = Kg + ((size_t)b * NN + k0) * DD;
#pragma unroll
    for (int i = 0; i < 8; i++) {      // Q: 128 rows
        int idx = tid + i * 256;
        int r = idx >> 4, c = (idx & 15) << 2;
        float4 v = *reinterpret_cast<const float4*>(Qb + r * DD + c);
        int base = r * TS + (c & ~7) + ((c >> 2) & 1);
        Qs[base + 0] = ftf32(v.x); Qs[base + 2] = ftf32(v.y);
        Qs[base + 4] = ftf32(v.z); Qs[base + 6] = ftf32(v.w);
    }
#pragma unroll
    for (int i = 0; i < 4; i++) {      // K: 64 rows
        int idx = tid + i * 256;
        int r = idx >> 4, c = (idx & 15) << 2;
        float4 v = *reinterpret_cast<const float4*>(Kb + r * DD + c);
        int base = r * TS + (c & ~7) + ((c >> 2) & 1);
        Ks[base + 0] = ftf32(v.x); Ks[base + 2] = ftf32(v.y);
        Ks[base + 4] = ftf32(v.z); Ks[base + 6] = ftf32(v.w);
    }
    __syncthreads();

    float cacc[8][4];
#pragma unroll
    for (int i = 0; i < 8; i++) { cacc[i][0] = cacc[i][1] = cacc[i][2] = cacc[i][3] = 0.f; }

#pragma unroll
    for (int kk = 0; kk < 64; kk += 8) {
        const float* qr = &Qs[(m0 + g) * TS + kk + 2 * tig];
        float2 A0 = *reinterpret_cast<const float2*>(qr);            // (g,tig),(g,tig+4)
        float2 A1 = *reinterpret_cast<const float2*>(qr + 8 * TS);   // (g+8,...)
#pragma unroll
        for (int nb = 0; nb < 8; nb++) {
            float2 Bf = *reinterpret_cast<const float2*>(&Ks[(nb * 8 + g) * TS + kk + 2 * tig]);
            mma_tf32(cacc[nb], A0.x, A1.x, A0.y, A1.y, Bf.x, Bf.y);
        }
    }

    // E store: lane owns (q=m0+g / +8, k = nb*8 + 2t, 2t+1)
    __half* Eb = g_E + (size_t)b * NN * NN;
#pragma unroll
    for (int nb = 0; nb < 8; nb++) {
        int col = k0 + nb * 8 + 2 * tig;
        int r1 = q0 + m0 + g;
        __half2 h0 = __floats2half2_rn(__expf(cacc[nb][0] * SCALE), __expf(cacc[nb][1] * SCALE));
        __half2 h1 = __floats2half2_rn(__expf(cacc[nb][2] * SCALE), __expf(cacc[nb][3] * SCALE));
        *reinterpret_cast<__half2*>(Eb + (size_t)r1 * NN + col) = h0;
        *reinterpret_cast<__half2*>(Eb + ((size_t)r1 + 8) * NN + col) = h1;
    }
}

// ---------------------------------------------------------------------------
// Kernel R: per (q,k): D = sum_b E[b,q,k];  E[b,q,k] *= 1/D  (in place)
// Each thread handles 8 consecutive (q,k) elements across all 16 b in regs.
// Exactly one 134MB read + one 134MB write.
// ---------------------------------------------------------------------------
__global__ __launch_bounds__(256)
void rescale_kernel() {
    const size_t grp = (size_t)blockIdx.x * 256 + threadIdx.x;   // 8 halves per group
    const size_t base = grp * 8;

    uint4 v[BB];
#pragma unroll
    for (int b = 0; b < BB; b++)
        v[b] = *reinterpret_cast<const uint4*>(g_E + (size_t)b * NN * NN + base);

    float s[8];
#pragma unroll
    for (int j = 0; j < 8; j++) s[j] = 0.f;
#pragma unroll
    for (int b = 0; b < BB; b++) {
        float2 f0 = __half22float2(*reinterpret_cast<const __half2*>(&v[b].x));
        float2 f1 = __half22float2(*reinterpret_cast<const __half2*>(&v[b].y));
        float2 f2 = __half22float2(*reinterpret_cast<const __half2*>(&v[b].z));
        float2 f3 = __half22float2(*reinterpret_cast<const __half2*>(&v[b].w));
        s[0] += f0.x; s[1] += f0.y; s[2] += f1.x; s[3] += f1.y;
        s[4] += f2.x; s[5] += f2.y; s[6] += f3.x; s[7] += f3.y;
    }
    float r[8];
#pragma unroll
    for (int j = 0; j < 8; j++) r[j] = 1.f / s[j];

#pragma unroll
    for (int b = 0; b < BB; b++) {
        uint4 o;
        float2 f0 = __half22float2(*reinterpret_cast<const __half2*>(&v[b].x));
        float2 f1 = __half22float2(*reinterpret_cast<const __half2*>(&v[b].y));
        float2 f2 = __half22float2(*reinterpret_cast<const __half2*>(&v[b].z));
        float2 f3 = __half22float2(*reinterpret_cast<const __half2*>(&v[b].w));
        *reinterpret_cast<__half2*>(&o.x) = __floats2half2_rn(f0.x * r[0], f0.y * r[1]);
        *reinterpret_cast<__half2*>(&o.y) = __floats2half2_rn(f1.x * r[2], f1.y * r[3]);
        *reinterpret_cast<__half2*>(&o.z) = __floats2half2_rn(f2.x * r[4], f2.y * r[5]);
        *reinterpret_cast<__half2*>(&o.w) = __floats2half2_rn(f3.x * r[6], f3.y * r[7]);
        *reinterpret_cast<uint4*>(g_E + (size_t)b * NN * NN + base) = o;
    }
}

// ---------------------------------------------------------------------------
// Kernel B: out[b,q,:] = sum_k P[b,q,k] * V[b,k,:]   (pure fp16 GEMM, P = g_E)
// Grid (32 qt, 16 b), 128 threads = 4 warps, q-tile 64.
// A-frags LDG'd straight from g_E; V -> fp16 smem, B-frags via ldmatrix.x4.trans.
// ---------------------------------------------------------------------------
#define VTS 72   // half-stride for Vs rows

__global__ __launch_bounds__(128, 5)
void pv_kernel(const float* __restrict__ V, float* __restrict__ out) {
    __shared__ __align__(16) __half Vs[64 * VTS];

    const int q0 = blockIdx.x * 64, b = blockIdx.y;
    const int tid = threadIdx.x;
    const int wid = tid >> 5, lane = tid & 31;
    const int g = lane >> 2, tig = lane & 3;
    const int m0 = wid * 16;

    // ldmatrix per-lane base: row = (lane&15), col = (lane>>4)*8
    const uint32_t vbase = smem_u32(Vs);
    const uint32_t lm_off = (uint32_t)(((lane & 15) * VTS + (lane >> 4) * 8) * 2);

    float oacc[8][4];
#pragma unroll
    for (int i = 0; i < 8; i++) { oacc[i][0] = oacc[i][1] = oacc[i][2] = oacc[i][3] = 0.f; }

    // E row base for this lane's A-fragments
    const __half* E0 = g_E + ((size_t)b * NN + q0 + m0 + g) * NN + 2 * tig;

    for (int kt = 0; kt < 32; kt++) {
        const int k0 = kt * 64;
        const float* Vb = V + ((size_t)b * NN + k0) * DD;

        __syncthreads();   // prior iteration done reading Vs
#pragma unroll
        for (int i = 0; i < 8; i++) {     // stage V tile 64x64 -> fp16 smem
            int idx = tid + i * 128;
            int r = idx >> 4, c = (idx & 15) << 2;
            float4 v = *reinterpret_cast<const float4*>(Vb + r * DD + c);
            __half2 h0 = __floats2half2_rn(v.x, v.y);
            __half2 h1 = __floats2half2_rn(v.z, v.w);
            *reinterpret_cast<uint2*>(&Vs[r * VTS + c]) = make_uint2(h2_u32(h0), h2_u32(h1));
        }
        __syncthreads();

#pragma unroll
        for (int kc = 0; kc < 4; kc++) {          // k-chunks of 16
            const int kk = kc * 16;
            const __half* Ep = E0 + k0 + kk;
            uint32_t a0 = *reinterpret_cast<const uint32_t*>(Ep);
            uint32_t a2 = *reinterpret_cast<const uint32_t*>(Ep + 8);
            uint32_t a1 = *reinterpret_cast<const uint32_t*>(Ep + (size_t)8 * NN);
            uint32_t a3 = *reinterpret_cast<const uint32_t*>(Ep + (size_t)8 * NN + 8);

#pragma unroll
            for (int dp = 0; dp < 4; dp++) {      // d-pairs of 16 cols
                uint32_t addr = vbase + lm_off + (uint32_t)((kk * VTS + dp * 16) * 2);
                uint32_t r0, r1, r2, r3;
                asm volatile(
                    "ldmatrix.sync.aligned.m8n8.x4.trans.shared.b16 {%0,%1,%2,%3}, [%4];"
                    : "=r"(r0), "=r"(r1), "=r"(r2), "=r"(r3) : "r"(addr));
                mma_f16(oacc[dp * 2 + 0], a0, a1, a2, a3, r0, r1);
                mma_f16(oacc[dp * 2 + 1], a0, a1, a2, a3, r2, r3);
            }
        }
    }

    // Write output: lane owns O[q=m0+g / +8][d = n0*8 + 2t, 2t+1]
    float* ob = out + ((size_t)b * NN + q0 + m0) * DD;
#pragma unroll
    for (int nb = 0; nb < 8; nb++) {
        int col = nb * 8 + 2 * tig;
        *reinterpret_cast<float2*>(&ob[(size_t)g * DD + col]) =
            make_float2(oacc[nb][0], oacc[nb][1]);
        *reinterpret_cast<float2*>(&ob[((size_t)g + 8) * DD + col]) =
            make_float2(oacc[nb][2], oacc[nb][3]);
    }
}

extern "C" void kernel_launch(void* const* d_in, const int* in_sizes, int n_in,
                              void* d_out, int out_size) {
    const float* Q = (const float*)d_in[0];
    const float* K = (const float*)d_in[1];
    const float* V = (const float*)d_in[2];
    float* out = (float*)d_out;

    const int smem1 = 192 * TS * (int)sizeof(float);   // 55296 B
    cudaFuncSetAttribute(qk_exp_kernel, cudaFuncAttributeMaxDynamicSharedMemorySize, smem1);

    qk_exp_kernel<<<dim3(32, 16, 16), 256, smem1>>>(Q, K);
    rescale_kernel<<<(NN * NN / 8) / 256, 256>>>();
    pv_kernel<<<dim3(32, 16), 128>>>(V, out);
}

// round 7
// speedup vs baseline: 1.5099x; 1.1594x over previous
#include <cuda_runtime.h>
#include <cuda_fp16.h>
#include <cstdint>

#define BB 16
#define NN 2048
#define DD 64
#define SCALE 0.125f
#define HTS 72   // smem row stride in halves: 144B rows -> conflict-free ldmatrix

// 134 MB fp16 scratch: E[b][q][k] = exp(scale * S)  (raw, NOT rescaled)
__device__ __half g_E[(size_t)BB * NN * NN];
// 16 MB fp32 scratch: rd[q][k] = 1 / sum_b E[b][q][k]
__device__ float g_rd[(size_t)NN * NN];

__device__ __forceinline__ uint32_t smem_u32(const void* p) {
    uint32_t a;
    asm("{ .reg .u64 t; cvta.to.shared.u64 t, %1; cvt.u32.u64 %0, t; }" : "=r"(a) : "l"(p));
    return a;
}

__device__ __forceinline__ uint32_t h2_u32(__half2 h) {
    union { __half2 h; uint32_t u; } cvt; cvt.h = h; return cvt.u;
}
__device__ __forceinline__ __half2 u32_h2(uint32_t u) {
    union { uint32_t u; __half2 h; } cvt; cvt.u = u; return cvt.h;
}

__device__ __forceinline__ void mma_f16(float c[4], uint32_t a0, uint32_t a1,
                                        uint32_t a2, uint32_t a3,
                                        uint32_t b0, uint32_t b1) {
    asm volatile(
        "mma.sync.aligned.m16n8k16.row.col.f32.f16.f16.f32 "
        "{%0,%1,%2,%3}, {%4,%5,%6,%7}, {%8,%9}, {%0,%1,%2,%3};"
        : "+f"(c[0]), "+f"(c[1]), "+f"(c[2]), "+f"(c[3])
        : "r"(a0), "r"(a1), "r"(a2), "r"(a3), "r"(b0), "r"(b1));
}

#define LDMATRIX_X4(r0, r1, r2, r3, addr) \
    asm volatile("ldmatrix.sync.aligned.m8n8.x4.shared.b16 {%0,%1,%2,%3}, [%4];" \
                 : "=r"(r0), "=r"(r1), "=r"(r2), "=r"(r3) : "r"(addr))

// ---------------------------------------------------------------------------
// Kernel 1: E[b,q,k] = exp(scale * Q[b,q,:].K[b,k,:])    (fp16 in, fp16 out)
// Grid (32 kt, 16 qt, 16 b), 256 threads = 8 warps, tile 128q x 64k.
// ---------------------------------------------------------------------------
__global__ __launch_bounds__(256)
void qk_exp_kernel(const float* __restrict__ Q, const float* __restrict__ Kg) {
    __shared__ __align__(16) __half Qs[128 * HTS];
    __shared__ __align__(16) __half Ks[64 * HTS];

    const int q0 = blockIdx.y * 128, k0 = blockIdx.x * 64, b = blockIdx.z;
    const int tid = threadIdx.x;
    const int wid = tid >> 5, lane = tid & 31;
    const int g = lane >> 2, tig = lane & 3;
    const int m0 = wid * 16;

    const float* Qb = Q + ((size_t)b * NN + q0) * DD;
    const float* Kb = Kg + ((size_t)b * NN + k0) * DD;
#pragma unroll
    for (int i = 0; i < 8; i++) {      // Q: 128 rows x 64
        int idx = tid + i * 256;
        int r = idx >> 4, c = (idx & 15) << 2;
        float4 v = *reinterpret_cast<const float4*>(Qb + r * DD + c);
        *reinterpret_cast<uint2*>(&Qs[r * HTS + c]) =
            make_uint2(h2_u32(__floats2half2_rn(v.x, v.y)), h2_u32(__floats2half2_rn(v.z, v.w)));
    }
#pragma unroll
    for (int i = 0; i < 4; i++) {      // K: 64 rows x 64
        int idx = tid + i * 256;
        int r = idx >> 4, c = (idx & 15) << 2;
        float4 v = *reinterpret_cast<const float4*>(Kb + r * DD + c);
        *reinterpret_cast<uint2*>(&Ks[r * HTS + c]) =
            make_uint2(h2_u32(__floats2half2_rn(v.x, v.y)), h2_u32(__floats2half2_rn(v.z, v.w)));
    }
    __syncthreads();

    const uint32_t qbase = smem_u32(Qs), kbase = smem_u32(Ks);
    const int lmrow = lane & 15, lmcol = (lane >> 4) * 8;

    float cacc[8][4];
#pragma unroll
    for (int i = 0; i < 8; i++) { cacc[i][0] = cacc[i][1] = cacc[i][2] = cacc[i][3] = 0.f; }

#pragma unroll
    for (int kc = 0; kc < 4; kc++) {
        const int kk = kc * 16;
        uint32_t a0, a1, a2, a3;
        LDMATRIX_X4(a0, a1, a2, a3,
                    qbase + (uint32_t)(((m0 + lmrow) * HTS + kk + lmcol) * 2));
#pragma unroll
        for (int nb2 = 0; nb2 < 4; nb2++) {
            uint32_t r0, r1, r2, r3;
            LDMATRIX_X4(r0, r1, r2, r3,
                        kbase + (uint32_t)(((nb2 * 16 + lmrow) * HTS + kk + lmcol) * 2));
            mma_f16(cacc[nb2 * 2 + 0], a0, a1, a2, a3, r0, r2);
            mma_f16(cacc[nb2 * 2 + 1], a0, a1, a2, a3, r1, r3);
        }
    }

    // E store: lane owns (q = m0+g / +8, k = nb*8 + 2t, 2t+1)
    __half* Eb = g_E + (size_t)b * NN * NN;
#pragma unroll
    for (int nb = 0; nb < 8; nb++) {
        int col = k0 + nb * 8 + 2 * tig;
        int r1 = q0 + m0 + g;
        __half2 h0 = __floats2half2_rn(__expf(cacc[nb][0] * SCALE), __expf(cacc[nb][1] * SCALE));
        __half2 h1 = __floats2half2_rn(__expf(cacc[nb][2] * SCALE), __expf(cacc[nb][3] * SCALE));
        *reinterpret_cast<__half2*>(Eb + (size_t)r1 * NN + col) = h0;
        *reinterpret_cast<__half2*>(Eb + ((size_t)r1 + 8) * NN + col) = h1;
    }
}

// ---------------------------------------------------------------------------
// Kernel R: rd[q,k] = 1 / sum_b E[b,q,k]   (fp32; E is NOT modified)
// Each thread: 8 consecutive (q,k), all 16 b in regs. 134MB read + 16MB write.
// ---------------------------------------------------------------------------
__global__ __launch_bounds__(256)
void rescale_kernel() {
    const size_t grp = (size_t)blockIdx.x * 256 + threadIdx.x;
    const size_t base = grp * 8;

    float s[8];
#pragma unroll
    for (int j = 0; j < 8; j++) s[j] = 0.f;
#pragma unroll
    for (int b = 0; b < BB; b++) {
        uint4 v = *reinterpret_cast<const uint4*>(g_E + (size_t)b * NN * NN + base);
        float2 f0 = __half22float2(u32_h2(v.x));
        float2 f1 = __half22float2(u32_h2(v.y));
        float2 f2 = __half22float2(u32_h2(v.z));
        float2 f3 = __half22float2(u32_h2(v.w));
        s[0] += f0.x; s[1] += f0.y; s[2] += f1.x; s[3] += f1.y;
        s[4] += f2.x; s[5] += f2.y; s[6] += f3.x; s[7] += f3.y;
    }
    float4 o0 = make_float4(1.f / s[0], 1.f / s[1], 1.f / s[2], 1.f / s[3]);
    float4 o1 = make_float4(1.f / s[4], 1.f / s[5], 1.f / s[6], 1.f / s[7]);
    *reinterpret_cast<float4*>(g_rd + base) = o0;
    *reinterpret_cast<float4*>(g_rd + base + 4) = o1;
}

// ---------------------------------------------------------------------------
// Kernel B: out[b,q,:] = sum_k (E[b,q,k]*rd[q,k]) * V[b,k,:]
// Grid (32 qt, 16 b), 128 threads = 4 warps, q-tile 64.
// A-frags = LDG(E) * LDG(rd) fused in regs; V via ldmatrix.x4.trans fp16 smem.
// ---------------------------------------------------------------------------
__global__ __launch_bounds__(128, 5)
void pv_kernel(const float* __restrict__ V, float* __restrict__ out) {
    __shared__ __align__(16) __half Vs[64 * HTS];

    const int q0 = blockIdx.x * 64, b = blockIdx.y;
    const int tid = threadIdx.x;
    const int wid = tid >> 5, lane = tid & 31;
    const int g = lane >> 2, tig = lane & 3;
    const int m0 = wid * 16;

    const uint32_t vbase = smem_u32(Vs);
    const uint32_t lm_off = (uint32_t)(((lane & 15) * HTS + (lane >> 4) * 8) * 2);

    float oacc[8][4];
#pragma unroll
    for (int i = 0; i < 8; i++) { oacc[i][0] = oacc[i][1] = oacc[i][2] = oacc[i][3] = 0.f; }

    const __half* E0 = g_E + ((size_t)b * NN + q0 + m0 + g) * NN + 2 * tig;
    const float* R0 = g_rd + ((size_t)(q0 + m0 + g)) * NN + 2 * tig;

    for (int kt = 0; kt < 32; kt++) {
        const int k0 = kt * 64;
        const float* Vb = V + ((size_t)b * NN + k0) * DD;

        __syncthreads();   // prior iteration done reading Vs
#pragma unroll
        for (int i = 0; i < 8; i++) {     // stage V tile 64x64 -> fp16 smem
            int idx = tid + i * 128;
            int r = idx >> 4, c = (idx & 15) << 2;
            float4 v = *reinterpret_cast<const float4*>(Vb + r * DD + c);
            *reinterpret_cast<uint2*>(&Vs[r * HTS + c]) =
                make_uint2(h2_u32(__floats2half2_rn(v.x, v.y)),
                           h2_u32(__floats2half2_rn(v.z, v.w)));
        }
        __syncthreads();

#pragma unroll
        for (int kc = 0; kc < 4; kc++) {          // k-chunks of 16
            const int kk = kc * 16;
            const __half* Ep = E0 + k0 + kk;
            const float* Rp = R0 + k0 + kk;
            // raw E fragments
            uint32_t e0 = *reinterpret_cast<const uint32_t*>(Ep);
            uint32_t e2 = *reinterpret_cast<const uint32_t*>(Ep + 8);
            uint32_t e1 = *reinterpret_cast<const uint32_t*>(Ep + (size_t)8 * NN);
            uint32_t e3 = *reinterpret_cast<const uint32_t*>(Ep + (size_t)8 * NN + 8);
            // matching rd (fp32, heavily L2-reused across the 16 b-CTAs)
            float2 r0 = *reinterpret_cast<const float2*>(Rp);
            float2 r2 = *reinterpret_cast<const float2*>(Rp + 8);
            float2 r1 = *reinterpret_cast<const float2*>(Rp + (size_t)8 * NN);
            float2 r3 = *reinterpret_cast<const float2*>(Rp + (size_t)8 * NN + 8);
            // P = E * rd, rounded to fp16 once
            float2 f;
            f = __half22float2(u32_h2(e0));
            uint32_t a0 = h2_u32(__floats2half2_rn(f.x * r0.x, f.y * r0.y));
            f = __half22float2(u32_h2(e1));
            uint32_t a1 = h2_u32(__floats2half2_rn(f.x * r1.x, f.y * r1.y));
            f = __half22float2(u32_h2(e2));
            uint32_t a2 = h2_u32(__floats2half2_rn(f.x * r2.x, f.y * r2.y));
            f = __half22float2(u32_h2(e3));
            uint32_t a3 = h2_u32(__floats2half2_rn(f.x * r3.x, f.y * r3.y));

#pragma unroll
            for (int dp = 0; dp < 4; dp++) {      // d-pairs of 16 cols
                uint32_t addr = vbase + lm_off + (uint32_t)((kk * HTS + dp * 16) * 2);
                uint32_t b0, b1, b2, b3;
                asm volatile(
                    "ldmatrix.sync.aligned.m8n8.x4.trans.shared.b16 {%0,%1,%2,%3}, [%4];"
                    : "=r"(b0), "=r"(b1), "=r"(b2), "=r"(b3) : "r"(addr));
                mma_f16(oacc[dp * 2 + 0], a0, a1, a2, a3, b0, b1);
                mma_f16(oacc[dp * 2 + 1], a0, a1, a2, a3, b2, b3);
            }
        }
    }

    // Write output: lane owns O[q = m0+g / +8][d = nb*8 + 2t, 2t+1]
    float* ob = out + ((size_t)b * NN + q0 + m0) * DD;
#pragma unroll
    for (int nb = 0; nb < 8; nb++) {
        int col = nb * 8 + 2 * tig;
        *reinterpret_cast<float2*>(&ob[(size_t)g * DD + col]) =
            make_float2(oacc[nb][0], oacc[nb][1]);
        *reinterpret_cast<float2*>(&ob[((size_t)g + 8) * DD + col]) =
            make_float2(oacc[nb][2], oacc[nb][3]);
    }
}

extern "C" void kernel_launch(void* const* d_in, const int* in_sizes, int n_in,
                              void* d_out, int out_size) {
    const float* Q = (const float*)d_in[0];
    const float* K = (const float*)d_in[1];
    const float* V = (const float*)d_in[2];
    float* out = (float*)d_out;

    qk_exp_kernel<<<dim3(32, 16, 16), 256>>>(Q, K);
    rescale_kernel<<<(NN * NN / 8) / 256, 256>>>();
    pv_kernel<<<dim3(32, 16), 128>>>(V, out);
}